// round 14
// baseline (speedup 1.0000x reference)
#include <cuda_runtime.h>
#include <cuda_fp16.h>
#include <math.h>

#define DDIM 1024
#define HDIM 4096
#define ENUM 8
#define TMAX 8192
#define NSP  17408

#define BM 128
#define BN 128
#define BK 32
#define STG 2
#define ASTR 40   // smem row stride (halves): 80B, 16B-aligned, conflict-free

typedef unsigned int u32;

__device__ int    g_count[ENUM];
__device__ int    g_cntp[ENUM];
__device__ int    g_offset[ENUM];
__device__ int    g_total;
__device__ int    g_tok[ENUM * TMAX];
__device__ float  g_wgt[ENUM * TMAX];
__device__ u32    g_as_ep[2 * TMAX];

__device__ __half g_xbuf[(size_t)NSP * DDIM];
__device__ __half g_hbuf[(size_t)NSP * HDIM];
__device__ float  g_ybuf[(size_t)NSP * DDIM];
__device__ __half g_w1h[(size_t)ENUM * HDIM * DDIM];  // [e][n=H][k=D] fp16
__device__ __half g_w2h[(size_t)ENUM * DDIM * HDIM];  // [e][n=D][k=H] fp16

// INVARIANT: __device__ symbols are referenced ONLY inside device code.
// Host-side use yields the host BSS shadow, silently served via ATS/C2C
// (R5: zeros; R7: 40x slowdown).

// ---------------- helpers ----------------
__device__ __forceinline__ u32 smem_u32(const void* p) {
    u32 a;
    asm("{ .reg .u64 t; cvta.to.shared.u64 t, %1; cvt.u32.u64 %0, t; }" : "=r"(a) : "l"(p));
    return a;
}
__device__ __forceinline__ void cpasync16(u32 dst, const void* src) {
    asm volatile("cp.async.cg.shared.global [%0], [%1], 16;" :: "r"(dst), "l"(src) : "memory");
}
__device__ __forceinline__ void mmaop(float* c, const u32* a, const u32* b) {
    asm volatile(
        "mma.sync.aligned.m16n8k16.row.col.f32.f16.f16.f32 "
        "{%0,%1,%2,%3}, {%4,%5,%6,%7}, {%8,%9}, {%0,%1,%2,%3};"
        : "+f"(c[0]), "+f"(c[1]), "+f"(c[2]), "+f"(c[3])
        : "r"(a[0]), "r"(a[1]), "r"(a[2]), "r"(a[3]), "r"(b[0]), "r"(b[1]));
}
__device__ __forceinline__ float gelu_exact(float v) {
    return 0.5f * v * (1.0f + erff(v * 0.70710678118654752f));
}

// ---------------- support kernels ----------------
__global__ void zero_counts_kernel() {
    if (threadIdx.x < ENUM) g_count[threadIdx.x] = 0;
}

__global__ void router_kernel(const float* __restrict__ x,
                              const float* __restrict__ gate_w, int T) {
    int t = blockIdx.x * (blockDim.x / 32) + (threadIdx.x >> 5);
    int lane = threadIdx.x & 31;
    if (t >= T) return;
    const float* xr = x + (size_t)t * DDIM;
    float acc[ENUM];
#pragma unroll
    for (int e = 0; e < ENUM; e++) acc[e] = 0.f;
    for (int d = lane; d < DDIM; d += 32) {
        float xv = xr[d];
#pragma unroll
        for (int e = 0; e < ENUM; e++) acc[e] += xv * gate_w[e * DDIM + d];
    }
#pragma unroll
    for (int o = 16; o > 0; o >>= 1)
#pragma unroll
        for (int e = 0; e < ENUM; e++)
            acc[e] += __shfl_xor_sync(0xFFFFFFFFu, acc[e], o);
    if (lane == 0) {
        float m = acc[0];
#pragma unroll
        for (int e = 1; e < ENUM; e++) m = fmaxf(m, acc[e]);
        float p[ENUM], Z = 0.f;
#pragma unroll
        for (int e = 0; e < ENUM; e++) { p[e] = expf(acc[e] - m); Z += p[e]; }
#pragma unroll
        for (int e = 0; e < ENUM; e++) p[e] /= Z;
        int i1 = 0; float p1 = p[0];
#pragma unroll
        for (int e = 1; e < ENUM; e++) if (p[e] > p1) { p1 = p[e]; i1 = e; }
        int i2 = -1; float p2 = -1.f;
#pragma unroll
        for (int e = 0; e < ENUM; e++)
            if (e != i1 && p[e] > p2) { p2 = p[e]; i2 = e; }
        float inv = 1.f / (p1 + p2 + 1e-9f);
        int pos1 = atomicAdd(&g_count[i1], 1);
        g_tok[i1 * TMAX + pos1] = t;  g_wgt[i1 * TMAX + pos1] = p1 * inv;
        g_as_ep[2 * t + 0] = ((u32)i1 << 16) | (u32)pos1;
        int pos2 = atomicAdd(&g_count[i2], 1);
        g_tok[i2 * TMAX + pos2] = t;  g_wgt[i2 * TMAX + pos2] = p2 * inv;
        g_as_ep[2 * t + 1] = ((u32)i2 << 16) | (u32)pos2;
    }
}

__global__ void setup_kernel() {
    if (threadIdx.x == 0) {
        int acc = 0;
        for (int e = 0; e < ENUM; e++) {
            g_offset[e] = acc;
            int cp = (g_count[e] + 127) & ~127;
            g_cntp[e] = cp;
            acc += cp;
        }
        g_total = acc;
    }
}

__global__ void gather_kernel(const float* __restrict__ x) {
    int r = blockIdx.x;
    if (r >= g_total) return;
    int e = 0;
#pragma unroll
    for (int i = 1; i < ENUM; i++) if (r >= g_offset[i]) e = i;
    int local = r - g_offset[e];
    __half* dst = g_xbuf + (size_t)r * DDIM + threadIdx.x * 4;
    if (local < g_count[e]) {
        const float4 v = *(const float4*)(x + (size_t)g_tok[e * TMAX + local] * DDIM
                                          + threadIdx.x * 4);
        __half2 h01 = __floats2half2_rn(v.x, v.y);
        __half2 h23 = __floats2half2_rn(v.z, v.w);
        uint2 u;
        u.x = *(u32*)&h01; u.y = *(u32*)&h23;
        *(uint2*)dst = u;
    } else {
        *(uint2*)dst = make_uint2(0u, 0u);
    }
}

// convert + transpose: src [e][R][C] fp32 -> device symbol [e][C][R] fp16
template <bool W1>
__global__ void convert_kernel(const float* __restrict__ src) {
    constexpr int R = W1 ? DDIM : HDIM;
    constexpr int C = W1 ? HDIM : DDIM;
    __half* dstb = W1 ? g_w1h : g_w2h;
    __shared__ float ts[32][33];
    const float* s = src + (size_t)blockIdx.z * R * C;
    __half* d = dstb + (size_t)blockIdx.z * R * C;
    int c0 = blockIdx.x * 32, r0 = blockIdx.y * 32;
    int tx = threadIdx.x, ty = threadIdx.y;
#pragma unroll
    for (int i = 0; i < 32; i += 8)
        ts[ty + i][tx] = s[(size_t)(r0 + ty + i) * C + c0 + tx];
    __syncthreads();
#pragma unroll
    for (int i = 0; i < 32; i += 8)
        d[(size_t)(c0 + ty + i) * R + r0 + tx] = __float2half(ts[tx][ty + i]);
}

__global__ void combine_kernel(float* __restrict__ out) {
    int t = blockIdx.x;
    u32 e0 = g_as_ep[2 * t], e1 = g_as_ep[2 * t + 1];
    long r0 = (long)g_offset[e0 >> 16] + (e0 & 0xFFFF);
    long r1 = (long)g_offset[e1 >> 16] + (e1 & 0xFFFF);
    float4 a = ((const float4*)(g_ybuf + r0 * DDIM))[threadIdx.x];
    float4 b = ((const float4*)(g_ybuf + r1 * DDIM))[threadIdx.x];
    ((float4*)(out + (size_t)t * DDIM))[threadIdx.x] =
        make_float4(a.x + b.x, a.y + b.y, a.z + b.z, a.w + b.w);
}

// ---------------- fp16 mma.sync GEMM: 128x128x32, 2-stage, 1 sync/iter ----
// Loop order per kt: wait(kt ready) -> syncthreads -> issue cp.async(kt+1)
// -> compute(kt). The single barrier protects the 2-deep ring: the load for
// stage (kt+1)&1 is issued only after all warps finished reading it (at
// iteration kt-1, before the barrier at top of kt).
// G1: A=g_xbuf, B=g_w1h, Out=g_hbuf fp16, gelu(.+b1)
// !G1: A=g_hbuf, B=g_w2h, Out=g_ybuf fp32, wgt*(.+b2)
template <int KDIM, int ODIM, bool G1>
__global__ void __launch_bounds__(256)
moe_gemm(const float* __restrict__ bias) {
    constexpr int KT = KDIM / BK;
    const __half* A = G1 ? g_xbuf : g_hbuf;
    const __half* Bw = G1 ? g_w1h : g_w2h;

    const int e = blockIdx.z;
    const int m0 = blockIdx.y * BM;
    if (m0 >= g_cntp[e]) return;
    const int n0 = blockIdx.x * BN;
    const long arow0 = (long)g_offset[e] + m0;

    __shared__ __half Asm[STG][BM][ASTR];
    __shared__ __half Bsm[STG][BN][ASTR];

    const int tid = threadIdx.x;
    const int lane = tid & 31, wid = tid >> 5;
    const int wm = wid >> 2, wn = wid & 3;   // 2m x 4n warps, warp tile 64x32
    const int lr = lane >> 2, lc = lane & 3;

    const __half* Ae = A + arow0 * KDIM;
    const __half* Be = Bw + (size_t)e * ODIM * KDIM + (size_t)n0 * KDIM;

    float cr[4][4][4];
#pragma unroll
    for (int mi = 0; mi < 4; mi++)
#pragma unroll
        for (int ni = 0; ni < 4; ni++)
#pragma unroll
            for (int q = 0; q < 4; q++) cr[mi][ni][q] = 0.f;

    auto load_stage = [&](int kt, int buf) {
        const __half* as = Ae + kt * BK;
        const __half* bs = Be + kt * BK;
#pragma unroll
        for (int i = 0; i < 2; i++) {
            int c = tid + i * 256;
            int row = c >> 2, k8 = (c & 3) * 8;
            cpasync16(smem_u32(&Asm[buf][row][k8]), as + (size_t)row * KDIM + k8);
            cpasync16(smem_u32(&Bsm[buf][row][k8]), bs + (size_t)row * KDIM + k8);
        }
    };

    load_stage(0, 0);
    asm volatile("cp.async.commit_group;" ::: "memory");

#pragma unroll 1
    for (int kt = 0; kt < KT; kt++) {
        asm volatile("cp.async.wait_group 0;" ::: "memory");
        __syncthreads();

        if (kt + 1 < KT) {
            load_stage(kt + 1, (kt + 1) & 1);
            asm volatile("cp.async.commit_group;" ::: "memory");
        }

        const int buf = kt & 1;
#pragma unroll
        for (int kk = 0; kk < 2; kk++) {
            const int k0 = kk * 16 + 2 * lc;
            u32 af[4][4], bf[4][2];
#pragma unroll
            for (int mi = 0; mi < 4; mi++) {
                const __half* ap = &Asm[buf][wm * 64 + mi * 16 + lr][k0];
                af[mi][0] = *(const u32*)(ap);
                af[mi][1] = *(const u32*)(ap + 8 * ASTR);
                af[mi][2] = *(const u32*)(ap + 8);
                af[mi][3] = *(const u32*)(ap + 8 * ASTR + 8);
            }
#pragma unroll
            for (int ni = 0; ni < 4; ni++) {
                const __half* bp = &Bsm[buf][wn * 32 + ni * 8 + lr][k0];
                bf[ni][0] = *(const u32*)(bp);
                bf[ni][1] = *(const u32*)(bp + 8);
            }
#pragma unroll
            for (int mi = 0; mi < 4; mi++)
#pragma unroll
                for (int ni = 0; ni < 4; ni++)
                    mmaop(cr[mi][ni], af[mi], bf[ni]);
        }
    }

    // epilogue
    const float* bp = bias + (size_t)e * ODIM + n0 + wn * 32;
#pragma unroll
    for (int mi = 0; mi < 4; mi++) {
        int rlo = wm * 64 + mi * 16 + lr;
        int rhi = rlo + 8;
        float wlo = 1.f, whi = 1.f;
        if (!G1) {
            wlo = g_wgt[e * TMAX + m0 + rlo];
            whi = g_wgt[e * TMAX + m0 + rhi];
        }
#pragma unroll
        for (int ni = 0; ni < 4; ni++) {
            int col = ni * 8 + 2 * lc;
            float b0v = bp[col], b1v = bp[col + 1];
            float v0 = cr[mi][ni][0] + b0v, v1 = cr[mi][ni][1] + b1v;
            float v2 = cr[mi][ni][2] + b0v, v3 = cr[mi][ni][3] + b1v;
            if (G1) {
                __half* olo = g_hbuf + (arow0 + rlo) * (size_t)ODIM + n0 + wn * 32 + col;
                __half* ohi = g_hbuf + (arow0 + rhi) * (size_t)ODIM + n0 + wn * 32 + col;
                *(__half2*)olo = __floats2half2_rn(gelu_exact(v0), gelu_exact(v1));
                *(__half2*)ohi = __floats2half2_rn(gelu_exact(v2), gelu_exact(v3));
            } else {
                float* olo = g_ybuf + (arow0 + rlo) * (size_t)ODIM + n0 + wn * 32 + col;
                float* ohi = g_ybuf + (arow0 + rhi) * (size_t)ODIM + n0 + wn * 32 + col;
                *(float2*)olo = make_float2(v0 * wlo, v1 * wlo);
                *(float2*)ohi = make_float2(v2 * whi, v3 * whi);
            }
        }
    }
}

// ---------------- launch ----------------
extern "C" void kernel_launch(void* const* d_in, const int* in_sizes, int n_in,
                              void* d_out, int out_size) {
    const float* x      = (const float*)d_in[0];
    const float* gate_w = (const float*)d_in[1];
    const float* w1     = (const float*)d_in[2];
    const float* b1     = (const float*)d_in[3];
    const float* w2     = (const float*)d_in[4];
    const float* b2     = (const float*)d_in[5];
    float* out = (float*)d_out;
    const int T = in_sizes[0] / DDIM;

    zero_counts_kernel<<<1, 32>>>();
    router_kernel<<<(T + 7) / 8, 256>>>(x, gate_w, T);
    {
        dim3 g(HDIM / 32, DDIM / 32, ENUM), b(32, 8);
        convert_kernel<true><<<g, b>>>(w1);
    }
    {
        dim3 g(DDIM / 32, HDIM / 32, ENUM), b(32, 8);
        convert_kernel<false><<<g, b>>>(w2);
    }
    setup_kernel<<<1, 32>>>();
    gather_kernel<<<NSP, 256>>>(x);
    {
        dim3 g(HDIM / BN, TMAX / BM, ENUM);
        moe_gemm<DDIM, HDIM, true><<<g, 256>>>(b1);
    }
    {
        dim3 g(DDIM / BN, TMAX / BM, ENUM);
        moe_gemm<HDIM, DDIM, false><<<g, 256>>>(b2);
    }
    combine_kernel<<<T, 256>>>(out);
}

// round 15
// speedup vs baseline: 1.0004x; 1.0004x over previous
#include <cuda_runtime.h>
#include <cuda_fp16.h>
#include <math.h>

#define DDIM 1024
#define HDIM 4096
#define ENUM 8
#define TMAX 8192
#define NSP  17408

#define BM 128
#define BN 128
#define BK 32
#define STG 2
#define ASTR 40   // smem row stride (halves): 80B, 16B-aligned, conflict-free

typedef unsigned int u32;

__device__ int    g_count[ENUM];
__device__ int    g_cntp[ENUM];
__device__ int    g_offset[ENUM];
__device__ int    g_total;
__device__ int    g_tok[ENUM * TMAX];
__device__ float  g_wgt[ENUM * TMAX];
__device__ u32    g_as_ep[2 * TMAX];

__device__ __half g_xbuf[(size_t)NSP * DDIM];
__device__ __half g_hbuf[(size_t)NSP * HDIM];
__device__ float  g_ybuf[(size_t)NSP * DDIM];
__device__ __half g_w1h[(size_t)ENUM * HDIM * DDIM];  // [e][n=H][k=D] fp16
__device__ __half g_w2h[(size_t)ENUM * DDIM * HDIM];  // [e][n=D][k=H] fp16

// INVARIANT: __device__ symbols are referenced ONLY inside device code.
// Host-side use yields the host BSS shadow, silently served via ATS/C2C
// (R5: zeros; R7: 40x slowdown).

// ---------------- helpers ----------------
__device__ __forceinline__ u32 smem_u32(const void* p) {
    u32 a;
    asm("{ .reg .u64 t; cvta.to.shared.u64 t, %1; cvt.u32.u64 %0, t; }" : "=r"(a) : "l"(p));
    return a;
}
__device__ __forceinline__ void cpasync16(u32 dst, const void* src) {
    asm volatile("cp.async.cg.shared.global [%0], [%1], 16;" :: "r"(dst), "l"(src) : "memory");
}
__device__ __forceinline__ void mmaop(float* c, const u32* a, const u32* b) {
    asm volatile(
        "mma.sync.aligned.m16n8k16.row.col.f32.f16.f16.f32 "
        "{%0,%1,%2,%3}, {%4,%5,%6,%7}, {%8,%9}, {%0,%1,%2,%3};"
        : "+f"(c[0]), "+f"(c[1]), "+f"(c[2]), "+f"(c[3])
        : "r"(a[0]), "r"(a[1]), "r"(a[2]), "r"(a[3]), "r"(b[0]), "r"(b[1]));
}
__device__ __forceinline__ float gelu_exact(float v) {
    return 0.5f * v * (1.0f + erff(v * 0.70710678118654752f));
}

// ---------------- support kernels ----------------
__global__ void zero_counts_kernel() {
    if (threadIdx.x < ENUM) g_count[threadIdx.x] = 0;
}

__global__ void router_kernel(const float* __restrict__ x,
                              const float* __restrict__ gate_w, int T) {
    int t = blockIdx.x * (blockDim.x / 32) + (threadIdx.x >> 5);
    int lane = threadIdx.x & 31;
    if (t >= T) return;
    const float* xr = x + (size_t)t * DDIM;
    float acc[ENUM];
#pragma unroll
    for (int e = 0; e < ENUM; e++) acc[e] = 0.f;
    for (int d = lane; d < DDIM; d += 32) {
        float xv = xr[d];
#pragma unroll
        for (int e = 0; e < ENUM; e++) acc[e] += xv * gate_w[e * DDIM + d];
    }
#pragma unroll
    for (int o = 16; o > 0; o >>= 1)
#pragma unroll
        for (int e = 0; e < ENUM; e++)
            acc[e] += __shfl_xor_sync(0xFFFFFFFFu, acc[e], o);
    if (lane == 0) {
        float m = acc[0];
#pragma unroll
        for (int e = 1; e < ENUM; e++) m = fmaxf(m, acc[e]);
        float p[ENUM], Z = 0.f;
#pragma unroll
        for (int e = 0; e < ENUM; e++) { p[e] = expf(acc[e] - m); Z += p[e]; }
#pragma unroll
        for (int e = 0; e < ENUM; e++) p[e] /= Z;
        int i1 = 0; float p1 = p[0];
#pragma unroll
        for (int e = 1; e < ENUM; e++) if (p[e] > p1) { p1 = p[e]; i1 = e; }
        int i2 = -1; float p2 = -1.f;
#pragma unroll
        for (int e = 0; e < ENUM; e++)
            if (e != i1 && p[e] > p2) { p2 = p[e]; i2 = e; }
        float inv = 1.f / (p1 + p2 + 1e-9f);
        int pos1 = atomicAdd(&g_count[i1], 1);
        g_tok[i1 * TMAX + pos1] = t;  g_wgt[i1 * TMAX + pos1] = p1 * inv;
        g_as_ep[2 * t + 0] = ((u32)i1 << 16) | (u32)pos1;
        int pos2 = atomicAdd(&g_count[i2], 1);
        g_tok[i2 * TMAX + pos2] = t;  g_wgt[i2 * TMAX + pos2] = p2 * inv;
        g_as_ep[2 * t + 1] = ((u32)i2 << 16) | (u32)pos2;
    }
}

__global__ void setup_kernel() {
    if (threadIdx.x == 0) {
        int acc = 0;
        for (int e = 0; e < ENUM; e++) {
            g_offset[e] = acc;
            int cp = (g_count[e] + 127) & ~127;
            g_cntp[e] = cp;
            acc += cp;
        }
        g_total = acc;
    }
}

__global__ void gather_kernel(const float* __restrict__ x) {
    int r = blockIdx.x;
    if (r >= g_total) return;
    int e = 0;
#pragma unroll
    for (int i = 1; i < ENUM; i++) if (r >= g_offset[i]) e = i;
    int local = r - g_offset[e];
    __half* dst = g_xbuf + (size_t)r * DDIM + threadIdx.x * 4;
    if (local < g_count[e]) {
        const float4 v = *(const float4*)(x + (size_t)g_tok[e * TMAX + local] * DDIM
                                          + threadIdx.x * 4);
        __half2 h01 = __floats2half2_rn(v.x, v.y);
        __half2 h23 = __floats2half2_rn(v.z, v.w);
        uint2 u;
        u.x = *(u32*)&h01; u.y = *(u32*)&h23;
        *(uint2*)dst = u;
    } else {
        *(uint2*)dst = make_uint2(0u, 0u);
    }
}

// convert + transpose: src [e][R][C] fp32 -> device symbol [e][C][R] fp16
template <bool W1>
__global__ void convert_kernel(const float* __restrict__ src) {
    constexpr int R = W1 ? DDIM : HDIM;
    constexpr int C = W1 ? HDIM : DDIM;
    __half* dstb = W1 ? g_w1h : g_w2h;
    __shared__ float ts[32][33];
    const float* s = src + (size_t)blockIdx.z * R * C;
    __half* d = dstb + (size_t)blockIdx.z * R * C;
    int c0 = blockIdx.x * 32, r0 = blockIdx.y * 32;
    int tx = threadIdx.x, ty = threadIdx.y;
#pragma unroll
    for (int i = 0; i < 32; i += 8)
        ts[ty + i][tx] = s[(size_t)(r0 + ty + i) * C + c0 + tx];
    __syncthreads();
#pragma unroll
    for (int i = 0; i < 32; i += 8)
        d[(size_t)(c0 + ty + i) * R + r0 + tx] = __float2half(ts[tx][ty + i]);
}

__global__ void combine_kernel(float* __restrict__ out) {
    int t = blockIdx.x;
    u32 e0 = g_as_ep[2 * t], e1 = g_as_ep[2 * t + 1];
    long r0 = (long)g_offset[e0 >> 16] + (e0 & 0xFFFF);
    long r1 = (long)g_offset[e1 >> 16] + (e1 & 0xFFFF);
    float4 a = ((const float4*)(g_ybuf + r0 * DDIM))[threadIdx.x];
    float4 b = ((const float4*)(g_ybuf + r1 * DDIM))[threadIdx.x];
    ((float4*)(out + (size_t)t * DDIM))[threadIdx.x] =
        make_float4(a.x + b.x, a.y + b.y, a.z + b.z, a.w + b.w);
}

// ---------------- fp16 mma.sync GEMM: 128x128x32, 2-stage, 1 sync/iter ----
// Loop order per kt: wait(kt ready) -> syncthreads -> issue cp.async(kt+1)
// -> compute(kt). The single barrier protects the 2-deep ring: the load for
// stage (kt+1)&1 is issued only after all warps finished reading it (at
// iteration kt-1, before the barrier at top of kt).
// G1: A=g_xbuf, B=g_w1h, Out=g_hbuf fp16, gelu(.+b1)
// !G1: A=g_hbuf, B=g_w2h, Out=g_ybuf fp32, wgt*(.+b2)
template <int KDIM, int ODIM, bool G1>
__global__ void __launch_bounds__(256)
moe_gemm(const float* __restrict__ bias) {
    constexpr int KT = KDIM / BK;
    const __half* A = G1 ? g_xbuf : g_hbuf;
    const __half* Bw = G1 ? g_w1h : g_w2h;

    const int e = blockIdx.z;
    const int m0 = blockIdx.y * BM;
    if (m0 >= g_cntp[e]) return;
    const int n0 = blockIdx.x * BN;
    const long arow0 = (long)g_offset[e] + m0;

    __shared__ __half Asm[STG][BM][ASTR];
    __shared__ __half Bsm[STG][BN][ASTR];

    const int tid = threadIdx.x;
    const int lane = tid & 31, wid = tid >> 5;
    const int wm = wid >> 2, wn = wid & 3;   // 2m x 4n warps, warp tile 64x32
    const int lr = lane >> 2, lc = lane & 3;

    const __half* Ae = A + arow0 * KDIM;
    const __half* Be = Bw + (size_t)e * ODIM * KDIM + (size_t)n0 * KDIM;

    float cr[4][4][4];
#pragma unroll
    for (int mi = 0; mi < 4; mi++)
#pragma unroll
        for (int ni = 0; ni < 4; ni++)
#pragma unroll
            for (int q = 0; q < 4; q++) cr[mi][ni][q] = 0.f;

    auto load_stage = [&](int kt, int buf) {
        const __half* as = Ae + kt * BK;
        const __half* bs = Be + kt * BK;
#pragma unroll
        for (int i = 0; i < 2; i++) {
            int c = tid + i * 256;
            int row = c >> 2, k8 = (c & 3) * 8;
            cpasync16(smem_u32(&Asm[buf][row][k8]), as + (size_t)row * KDIM + k8);
            cpasync16(smem_u32(&Bsm[buf][row][k8]), bs + (size_t)row * KDIM + k8);
        }
    };

    load_stage(0, 0);
    asm volatile("cp.async.commit_group;" ::: "memory");

#pragma unroll 1
    for (int kt = 0; kt < KT; kt++) {
        asm volatile("cp.async.wait_group 0;" ::: "memory");
        __syncthreads();

        if (kt + 1 < KT) {
            load_stage(kt + 1, (kt + 1) & 1);
            asm volatile("cp.async.commit_group;" ::: "memory");
        }

        const int buf = kt & 1;
#pragma unroll
        for (int kk = 0; kk < 2; kk++) {
            const int k0 = kk * 16 + 2 * lc;
            u32 af[4][4], bf[4][2];
#pragma unroll
            for (int mi = 0; mi < 4; mi++) {
                const __half* ap = &Asm[buf][wm * 64 + mi * 16 + lr][k0];
                af[mi][0] = *(const u32*)(ap);
                af[mi][1] = *(const u32*)(ap + 8 * ASTR);
                af[mi][2] = *(const u32*)(ap + 8);
                af[mi][3] = *(const u32*)(ap + 8 * ASTR + 8);
            }
#pragma unroll
            for (int ni = 0; ni < 4; ni++) {
                const __half* bp = &Bsm[buf][wn * 32 + ni * 8 + lr][k0];
                bf[ni][0] = *(const u32*)(bp);
                bf[ni][1] = *(const u32*)(bp + 8);
            }
#pragma unroll
            for (int mi = 0; mi < 4; mi++)
#pragma unroll
                for (int ni = 0; ni < 4; ni++)
                    mmaop(cr[mi][ni], af[mi], bf[ni]);
        }
    }

    // epilogue
    const float* bp = bias + (size_t)e * ODIM + n0 + wn * 32;
#pragma unroll
    for (int mi = 0; mi < 4; mi++) {
        int rlo = wm * 64 + mi * 16 + lr;
        int rhi = rlo + 8;
        float wlo = 1.f, whi = 1.f;
        if (!G1) {
            wlo = g_wgt[e * TMAX + m0 + rlo];
            whi = g_wgt[e * TMAX + m0 + rhi];
        }
#pragma unroll
        for (int ni = 0; ni < 4; ni++) {
            int col = ni * 8 + 2 * lc;
            float b0v = bp[col], b1v = bp[col + 1];
            float v0 = cr[mi][ni][0] + b0v, v1 = cr[mi][ni][1] + b1v;
            float v2 = cr[mi][ni][2] + b0v, v3 = cr[mi][ni][3] + b1v;
            if (G1) {
                __half* olo = g_hbuf + (arow0 + rlo) * (size_t)ODIM + n0 + wn * 32 + col;
                __half* ohi = g_hbuf + (arow0 + rhi) * (size_t)ODIM + n0 + wn * 32 + col;
                *(__half2*)olo = __floats2half2_rn(gelu_exact(v0), gelu_exact(v1));
                *(__half2*)ohi = __floats2half2_rn(gelu_exact(v2), gelu_exact(v3));
            } else {
                float* olo = g_ybuf + (arow0 + rlo) * (size_t)ODIM + n0 + wn * 32 + col;
                float* ohi = g_ybuf + (arow0 + rhi) * (size_t)ODIM + n0 + wn * 32 + col;
                *(float2*)olo = make_float2(v0 * wlo, v1 * wlo);
                *(float2*)ohi = make_float2(v2 * whi, v3 * whi);
            }
        }
    }
}

// ---------------- launch ----------------
extern "C" void kernel_launch(void* const* d_in, const int* in_sizes, int n_in,
                              void* d_out, int out_size) {
    const float* x      = (const float*)d_in[0];
    const float* gate_w = (const float*)d_in[1];
    const float* w1     = (const float*)d_in[2];
    const float* b1     = (const float*)d_in[3];
    const float* w2     = (const float*)d_in[4];
    const float* b2     = (const float*)d_in[5];
    float* out = (float*)d_out;
    const int T = in_sizes[0] / DDIM;

    zero_counts_kernel<<<1, 32>>>();
    router_kernel<<<(T + 7) / 8, 256>>>(x, gate_w, T);
    {
        dim3 g(HDIM / 32, DDIM / 32, ENUM), b(32, 8);
        convert_kernel<true><<<g, b>>>(w1);
    }
    {
        dim3 g(DDIM / 32, HDIM / 32, ENUM), b(32, 8);
        convert_kernel<false><<<g, b>>>(w2);
    }
    setup_kernel<<<1, 32>>>();
    gather_kernel<<<NSP, 256>>>(x);
    {
        dim3 g(HDIM / BN, TMAX / BM, ENUM);
        moe_gemm<DDIM, HDIM, true><<<g, 256>>>(b1);
    }
    {
        dim3 g(DDIM / BN, TMAX / BM, ENUM);
        moe_gemm<HDIM, DDIM, false><<<g, 256>>>(b2);
    }
    combine_kernel<<<T, 256>>>(out);
}